// round 6
// baseline (speedup 1.0000x reference)
#include <cuda_runtime.h>
#include <cuda_fp16.h>
#include <cuda_pipeline.h>
#include <mma.h>
#include <math.h>

using namespace nvcuda;

// ---------------- model constants ----------------
#define VOCAB   64
#define DM      512
#define NS      32
#define NH      16
#define NL      4
#define DIN     1024
#define PH      64
#define CONV    1088
#define KC      4
#define DPROJ   2128
#define BB      4
#define SS      1024
#define TT      (BB*SS)
#define EPSV    1e-5f

// ---------------- fp32 scratch ----------------
#define OFF_H    0u
#define OFF_ZX   (OFF_H  + TT*DM)
#define OFF_XC   (OFF_ZX + TT*DPROJ)
#define OFF_B    (OFF_XC + TT*DIN)
#define OFF_C    (OFF_B  + TT*NS)
#define OFF_DT   (OFF_C  + TT*NS)
#define OFF_DA   (OFF_DT + TT*NH)
#define OFF_Y    (OFF_DA + TT*NH)
#define SCRATCH_TOTAL (OFF_Y + TT*DIN)
__device__ float g_scratch[SCRATCH_TOTAL];

// ---------------- fp16 hi/lo scratch ----------------
#define WIN_SZ  (NL*DM*DPROJ)
#define WOUT_SZ (NL*DIN*DM)
#define HEAD_SZ (DM*VOCAB)
#define U_SZ    (TT*DM)
#define G_SZ    (TT*DIN)

#define HO_WINH  0u
#define HO_WINL  (HO_WINH + WIN_SZ)
#define HO_WOUTH (HO_WINL + WIN_SZ)
#define HO_WOUTL (HO_WOUTH + WOUT_SZ)
#define HO_HEADH (HO_WOUTL + WOUT_SZ)
#define HO_HEADL (HO_HEADH + HEAD_SZ)
#define HO_UH    (HO_HEADL + HEAD_SZ)
#define HO_UL    (HO_UH + U_SZ)
#define HO_GH    (HO_UL + U_SZ)
#define HO_GL    (HO_GH + G_SZ)
#define HO_HH    (HO_GL + G_SZ)
#define HO_HL    (HO_HH + U_SZ)
#define HALF_TOTAL (HO_HL + U_SZ)
__device__ __half g_half[HALF_TOTAL];

// ---------------- embedding gather ----------------
__global__ void embed_kernel(const int* __restrict__ tok,
                             const float* __restrict__ emb,
                             float* __restrict__ h) {
    for (int i = blockIdx.x * blockDim.x + threadIdx.x; i < TT * DM;
         i += gridDim.x * blockDim.x) {
        int row = i >> 9;
        int d   = i & (DM - 1);
        h[i] = emb[tok[row] * DM + d];
    }
}

// ---------------- fp32 -> fp16 hi/lo split ----------------
__global__ void split_kernel(const float* __restrict__ x,
                             __half* __restrict__ hi,
                             __half* __restrict__ lo, int n) {
    for (int i = blockIdx.x * blockDim.x + threadIdx.x; i < n;
         i += gridDim.x * blockDim.x) {
        float v = x[i];
        __half p = __float2half_rn(v);
        hi[i] = p;
        lo[i] = __float2half_rn(v - __half2float(p));
    }
}

// ---------------- rmsnorm over D_MODEL=512 -> hi/lo fp16 --------------
__global__ void rmsnorm_kernel(const float* __restrict__ x,
                               const float* __restrict__ w,
                               __half* __restrict__ uhi,
                               __half* __restrict__ ulo) {
    int row = blockIdx.x;
    const float* xr = x + (size_t)row * DM;
    int t = threadIdx.x;
    float v0 = xr[t];
    float v1 = xr[t + 256];
    float ss = v0 * v0 + v1 * v1;
    #pragma unroll
    for (int o = 16; o; o >>= 1) ss += __shfl_down_sync(0xffffffffu, ss, o);
    __shared__ float red[8];
    if ((t & 31) == 0) red[t >> 5] = ss;
    __syncthreads();
    if (t < 8) {
        float r = red[t];
        #pragma unroll
        for (int o = 4; o; o >>= 1) r += __shfl_down_sync(0xffu, r, o);
        if (t == 0) red[0] = r;
    }
    __syncthreads();
    float scale = rsqrtf(red[0] * (1.0f / DM) + EPSV);
    float o0 = v0 * scale * w[t];
    float o1 = v1 * scale * w[t + 256];
    __half p0 = __float2half_rn(o0);
    __half p1 = __float2half_rn(o1);
    uhi[(size_t)row * DM + t]       = p0;
    ulo[(size_t)row * DM + t]       = __float2half_rn(o0 - __half2float(p0));
    uhi[(size_t)row * DM + t + 256] = p1;
    ulo[(size_t)row * DM + t + 256] = __float2half_rn(o1 - __half2float(p1));
}

// ---------------- fp16-split WMMA GEMM, 2-stage cp.async pipeline -----------
// C[M,N] = (Ah+Al)[M,K] @ (Bh+Bl)[K,N] + bias[N] (+res)
// Block tile 128x64, k-tile 32. 256 threads = 8 warps (4x2), warp tile 32x32.
#define HBM_ 128
#define HBN_ 64
#define HBK_ 32
#define ASTR 40
#define BSTR 72
#define A_STG (HBM_*ASTR)          // 5120 halves per stage
#define B_STG (HBK_*BSTR)          // 2304 halves per stage
#define HG_SMEM ((4*A_STG + 4*B_STG) * 2)   // 59392 bytes

extern __shared__ __align__(16) unsigned char hg_smem[];

__global__ void __launch_bounds__(256)
hgemm_kernel(const __half* __restrict__ Ah, const __half* __restrict__ Al,
             const __half* __restrict__ Bh, const __half* __restrict__ Bl,
             const float* __restrict__ bias, const float* __restrict__ res,
             float* __restrict__ C, int M, int N, int K)
{
    __half* sAh = (__half*)hg_smem;          // [2][A_STG]
    __half* sAl = sAh + 2 * A_STG;           // [2][A_STG]
    __half* sBh = sAl + 2 * A_STG;           // [2][B_STG]
    __half* sBl = sBh + 2 * B_STG;           // [2][B_STG]
    float*  sOut = (float*)hg_smem;

    int tid = threadIdx.x;
    int bm = blockIdx.y * HBM_;
    int bn = blockIdx.x * HBN_;

    int lane = tid & 31;
    int warp = tid >> 5;
    int wm = (warp >> 1) * 32;
    int wn = (warp & 1) * 32;

    int a_row0 = tid >> 2;
    int a_row1 = a_row0 + 64;
    int a_col  = (tid & 3) * 8;
    int b_row = tid >> 3;
    int b_col = (tid & 7) * 8;
    bool bvalid = (bn + b_col + 8 <= N);

    wmma::fragment<wmma::accumulator, 16, 16, 16, float> acc[2][2];
    #pragma unroll
    for (int mi = 0; mi < 2; mi++) {
        #pragma unroll
        for (int ni = 0; ni < 2; ni++) {
            wmma::fill_fragment(acc[mi][ni], 0.0f);
        }
    }

    int KT = K / HBK_;

    // zero-fill invalid B region once for both stages (stays zero; loads skip it)
    if (!bvalid) {
        uint4 z;
        z.x = 0u; z.y = 0u; z.z = 0u; z.w = 0u;
        *(uint4*)(sBh + b_row * BSTR + b_col) = z;
        *(uint4*)(sBh + B_STG + b_row * BSTR + b_col) = z;
        *(uint4*)(sBl + b_row * BSTR + b_col) = z;
        *(uint4*)(sBl + B_STG + b_row * BSTR + b_col) = z;
    }
    __syncthreads();

    // ---- prologue: async-load stage 0 ----
    {
        int k0 = 0;
        __pipeline_memcpy_async(sAh + a_row0 * ASTR + a_col,
                                Ah + (size_t)(bm + a_row0) * K + k0 + a_col, 16);
        __pipeline_memcpy_async(sAh + a_row1 * ASTR + a_col,
                                Ah + (size_t)(bm + a_row1) * K + k0 + a_col, 16);
        __pipeline_memcpy_async(sAl + a_row0 * ASTR + a_col,
                                Al + (size_t)(bm + a_row0) * K + k0 + a_col, 16);
        __pipeline_memcpy_async(sAl + a_row1 * ASTR + a_col,
                                Al + (size_t)(bm + a_row1) * K + k0 + a_col, 16);
        if (bvalid) {
            __pipeline_memcpy_async(sBh + b_row * BSTR + b_col,
                                    Bh + (size_t)(k0 + b_row) * N + bn + b_col, 16);
            __pipeline_memcpy_async(sBl + b_row * BSTR + b_col,
                                    Bl + (size_t)(k0 + b_row) * N + bn + b_col, 16);
        }
        __pipeline_commit();
    }

    for (int kt = 0; kt < KT; kt++) {
        if (kt + 1 < KT) {
            int st = (kt + 1) & 1;
            int k0 = (kt + 1) * HBK_;
            __half* dAh = sAh + st * A_STG;
            __half* dAl = sAl + st * A_STG;
            __half* dBh = sBh + st * B_STG;
            __half* dBl = sBl + st * B_STG;
            __pipeline_memcpy_async(dAh + a_row0 * ASTR + a_col,
                                    Ah + (size_t)(bm + a_row0) * K + k0 + a_col, 16);
            __pipeline_memcpy_async(dAh + a_row1 * ASTR + a_col,
                                    Ah + (size_t)(bm + a_row1) * K + k0 + a_col, 16);
            __pipeline_memcpy_async(dAl + a_row0 * ASTR + a_col,
                                    Al + (size_t)(bm + a_row0) * K + k0 + a_col, 16);
            __pipeline_memcpy_async(dAl + a_row1 * ASTR + a_col,
                                    Al + (size_t)(bm + a_row1) * K + k0 + a_col, 16);
            if (bvalid) {
                __pipeline_memcpy_async(dBh + b_row * BSTR + b_col,
                                        Bh + (size_t)(k0 + b_row) * N + bn + b_col, 16);
                __pipeline_memcpy_async(dBl + b_row * BSTR + b_col,
                                        Bl + (size_t)(k0 + b_row) * N + bn + b_col, 16);
            }
            __pipeline_commit();
            __pipeline_wait_prior(1);
        } else {
            __pipeline_wait_prior(0);
        }
        __syncthreads();

        // ---- compute stage kt&1 ----
        {
            int st = kt & 1;
            __half* pAh = sAh + st * A_STG;
            __half* pAl = sAl + st * A_STG;
            __half* pBh = sBh + st * B_STG;
            __half* pBl = sBl + st * B_STG;
            #pragma unroll
            for (int kc = 0; kc < 2; kc++) {
                wmma::fragment<wmma::matrix_a, 16, 16, 16, half, wmma::row_major> fah[2];
                wmma::fragment<wmma::matrix_a, 16, 16, 16, half, wmma::row_major> fal[2];
                wmma::fragment<wmma::matrix_b, 16, 16, 16, half, wmma::row_major> fbh[2];
                wmma::fragment<wmma::matrix_b, 16, 16, 16, half, wmma::row_major> fbl[2];
                #pragma unroll
                for (int mi = 0; mi < 2; mi++) {
                    wmma::load_matrix_sync(fah[mi], pAh + (wm + mi * 16) * ASTR + kc * 16, ASTR);
                    wmma::load_matrix_sync(fal[mi], pAl + (wm + mi * 16) * ASTR + kc * 16, ASTR);
                }
                #pragma unroll
                for (int ni = 0; ni < 2; ni++) {
                    wmma::load_matrix_sync(fbh[ni], pBh + (kc * 16) * BSTR + wn + ni * 16, BSTR);
                    wmma::load_matrix_sync(fbl[ni], pBl + (kc * 16) * BSTR + wn + ni * 16, BSTR);
                }
                #pragma unroll
                for (int mi = 0; mi < 2; mi++) {
                    #pragma unroll
                    for (int ni = 0; ni < 2; ni++) {
                        wmma::mma_sync(acc[mi][ni], fah[mi], fbh[ni], acc[mi][ni]);
                        wmma::mma_sync(acc[mi][ni], fah[mi], fbl[ni], acc[mi][ni]);
                        wmma::mma_sync(acc[mi][ni], fal[mi], fbh[ni], acc[mi][ni]);
                    }
                }
            }
        }
        __syncthreads();
    }

    // ---- epilogue: park accumulators in smem, then guarded global stores ----
    float* myOut = sOut + warp * 1024;
    #pragma unroll
    for (int mi = 0; mi < 2; mi++) {
        #pragma unroll
        for (int ni = 0; ni < 2; ni++) {
            wmma::store_matrix_sync(myOut + mi * 16 * 32 + ni * 16,
                                    acc[mi][ni], 32, wmma::mem_row_major);
        }
    }
    __syncwarp();
    int colg = bn + wn + lane;
    if (colg < N) {
        float bc = bias[colg];
        #pragma unroll 4
        for (int r = 0; r < 32; r++) {
            int rowg = bm + wm + r;
            float v = myOut[r * 32 + lane] + bc;
            size_t off = (size_t)rowg * N + colg;
            if (res) v += res[off];
            C[off] = v;
        }
    }
}

// ---------------- causal depthwise conv + silu (sliding window) -------------
// grid: (ceil(CONV/128), SS/128, BB); block: 128 threads, thread = channel.
#define CTS 128
__global__ void __launch_bounds__(128)
conv_kernel(const float* __restrict__ zx,
            const float* __restrict__ cw,
            const float* __restrict__ cb,
            float* __restrict__ xc,
            float* __restrict__ Bm,
            float* __restrict__ Cm) {
    int c = blockIdx.x * 128 + threadIdx.x;
    if (c >= CONV) return;
    int b = blockIdx.z;
    int t0 = blockIdx.y * CTS;

    float w0 = cw[c * KC + 0];
    float w1 = cw[c * KC + 1];
    float w2 = cw[c * KC + 2];
    float w3 = cw[c * KC + 3];
    float bias = cb[c];

    const float* base = zx + (size_t)(b * SS) * DPROJ + DIN + c;

    float x0 = (t0 - 3 >= 0) ? base[(size_t)(t0 - 3) * DPROJ] : 0.0f;
    float x1 = (t0 - 2 >= 0) ? base[(size_t)(t0 - 2) * DPROJ] : 0.0f;
    float x2 = (t0 - 1 >= 0) ? base[(size_t)(t0 - 1) * DPROJ] : 0.0f;

    for (int t = t0; t < t0 + CTS; t++) {
        float x3 = base[(size_t)t * DPROJ];
        float acc = bias + w0 * x0 + w1 * x1 + w2 * x2 + w3 * x3;
        float s = acc / (1.0f + expf(-acc));
        int row = b * SS + t;
        if (c < DIN)            xc[(size_t)row * DIN + c] = s;
        else if (c < DIN + NS)  Bm[(size_t)row * NS + (c - DIN)] = s;
        else                    Cm[(size_t)row * NS + (c - DIN - NS)] = s;
        x0 = x1;
        x1 = x2;
        x2 = x3;
    }
}

// ---------------- dt softplus + dA ----------------
__global__ void dt_kernel(const float* __restrict__ zx,
                          const float* __restrict__ dtb,
                          const float* __restrict__ Alog,
                          float* __restrict__ dtO,
                          float* __restrict__ dAO) {
    int i = blockIdx.x * blockDim.x + threadIdx.x;
    if (i >= TT * NH) return;
    int row = i >> 4;
    int hh = i & 15;
    float v = zx[(size_t)row * DPROJ + DIN + CONV + hh] + dtb[hh];
    float sp = (v > 20.0f) ? v : log1pf(expf(v));
    dtO[i] = sp;
    dAO[i] = expf(sp * (-expf(Alog[hh])));
}

// ---------------- SSD sequential scan -----------------------------------
#define SCAN_TS 16
__global__ void __launch_bounds__(128)
scan_kernel(const float* __restrict__ xc, const float* __restrict__ Bm,
            const float* __restrict__ Cm, const float* __restrict__ dt,
            const float* __restrict__ dA, const float* __restrict__ Dp,
            float* __restrict__ y) {
    int blk = blockIdx.x;
    int pch = blk & 3;
    int bh  = blk >> 2;
    int b   = bh >> 4;
    int hh  = bh & 15;
    int tid = threadIdx.x;
    int pl  = tid >> 3;
    int ns  = tid & 7;
    int p   = pch * 16 + pl;

    __shared__ float4 sB[SCAN_TS][8];
    __shared__ float4 sC[SCAN_TS][8];
    __shared__ float  sx[SCAN_TS][16];
    __shared__ float  sdA[SCAN_TS];
    __shared__ float  sdt[SCAN_TS];

    float h0 = 0.f, h1 = 0.f, h2 = 0.f, h3 = 0.f;
    float dparam = Dp[hh];
    int rowbase = b * SS;

    for (int t0 = 0; t0 < SS; t0 += SCAN_TS) {
        {
            int ts = tid >> 3;
            int nf = tid & 7;
            int row = rowbase + t0 + ts;
            sB[ts][nf] = ((const float4*)(Bm + (size_t)row * NS))[nf];
            sC[ts][nf] = ((const float4*)(Cm + (size_t)row * NS))[nf];
        }
        for (int i = tid; i < SCAN_TS * 16; i += 128) {
            int ts = i >> 4;
            int ppl = i & 15;
            int row = rowbase + t0 + ts;
            sx[ts][ppl] = xc[(size_t)row * DIN + hh * PH + pch * 16 + ppl];
        }
        if (tid < SCAN_TS) {
            int row = rowbase + t0 + tid;
            sdA[tid] = dA[row * NH + hh];
            sdt[tid] = dt[row * NH + hh];
        }
        __syncthreads();

        #pragma unroll 4
        for (int ts = 0; ts < SCAN_TS; ts++) {
            float a    = sdA[ts];
            float xval = sx[ts][pl];
            float dtx  = sdt[ts] * xval;
            float4 Bv = sB[ts][ns];
            float4 Cv = sC[ts][ns];
            h0 = fmaf(a, h0, dtx * Bv.x);
            h1 = fmaf(a, h1, dtx * Bv.y);
            h2 = fmaf(a, h2, dtx * Bv.z);
            h3 = fmaf(a, h3, dtx * Bv.w);
            float acc = h0 * Cv.x;
            acc = fmaf(h1, Cv.y, acc);
            acc = fmaf(h2, Cv.z, acc);
            acc = fmaf(h3, Cv.w, acc);
            acc += __shfl_down_sync(0xffffffffu, acc, 4, 8);
            acc += __shfl_down_sync(0xffffffffu, acc, 2, 8);
            acc += __shfl_down_sync(0xffffffffu, acc, 1, 8);
            if (ns == 0) {
                int row = rowbase + t0 + ts;
                y[(size_t)row * DIN + hh * PH + p] = fmaf(xval, dparam, acc);
            }
        }
        __syncthreads();
    }
}

// ---------------- gate (y * silu(z)) + rmsnorm over D_INNER -> hi/lo --------
__global__ void gate_norm_kernel(const float* __restrict__ y,
                                 const float* __restrict__ zx,
                                 const float* __restrict__ gw,
                                 __half* __restrict__ ghi,
                                 __half* __restrict__ glo) {
    int row = blockIdx.x;
    __shared__ float sv[DIN];
    __shared__ float red[8];
    float ss = 0.0f;
    for (int c = threadIdx.x; c < DIN; c += blockDim.x) {
        float z = zx[(size_t)row * DPROJ + c];
        float v = y[(size_t)row * DIN + c] * (z / (1.0f + expf(-z)));
        sv[c] = v;
        ss += v * v;
    }
    #pragma unroll
    for (int o = 16; o; o >>= 1) ss += __shfl_down_sync(0xffffffffu, ss, o);
    if ((threadIdx.x & 31) == 0) red[threadIdx.x >> 5] = ss;
    __syncthreads();
    if (threadIdx.x < 8) {
        float r = red[threadIdx.x];
        #pragma unroll
        for (int o = 4; o; o >>= 1) r += __shfl_down_sync(0xffu, r, o);
        if (threadIdx.x == 0) red[0] = r;
    }
    __syncthreads();
    float scale = rsqrtf(red[0] * (1.0f / DIN) + EPSV);
    for (int c = threadIdx.x; c < DIN; c += blockDim.x) {
        float v = sv[c] * scale * gw[c];
        __half p = __float2half_rn(v);
        ghi[(size_t)row * DIN + c] = p;
        glo[(size_t)row * DIN + c] = __float2half_rn(v - __half2float(p));
    }
}

// ---------------- launch ----------------
extern "C" void kernel_launch(void* const* d_in, const int* in_sizes, int n_in,
                              void* d_out, int out_size) {
    const int*   tok     = (const int*)  d_in[0];
    const float* emb     = (const float*)d_in[1];
    const float* norm_w  = (const float*)d_in[2];
    const float* W_in    = (const float*)d_in[3];
    const float* b_in    = (const float*)d_in[4];
    const float* conv_w  = (const float*)d_in[5];
    const float* conv_b  = (const float*)d_in[6];
    const float* dt_bias = (const float*)d_in[7];
    const float* A_log   = (const float*)d_in[8];
    const float* D_param = (const float*)d_in[9];
    const float* gnorm_w = (const float*)d_in[10];
    const float* W_out   = (const float*)d_in[11];
    const float* b_out   = (const float*)d_in[12];
    const float* head_w  = (const float*)d_in[13];
    const float* head_b  = (const float*)d_in[14];

    float* scratch = nullptr;
    cudaGetSymbolAddress((void**)&scratch, g_scratch);
    __half* hs = nullptr;
    cudaGetSymbolAddress((void**)&hs, g_half);

    float* gh  = scratch + OFF_H;
    float* gzx = scratch + OFF_ZX;
    float* gxc = scratch + OFF_XC;
    float* gB  = scratch + OFF_B;
    float* gC  = scratch + OFF_C;
    float* gdt = scratch + OFF_DT;
    float* gdA = scratch + OFF_DA;
    float* gy  = scratch + OFF_Y;

    __half* WinH  = hs + HO_WINH;
    __half* WinL  = hs + HO_WINL;
    __half* WoutH = hs + HO_WOUTH;
    __half* WoutL = hs + HO_WOUTL;
    __half* HeadH = hs + HO_HEADH;
    __half* HeadL = hs + HO_HEADL;
    __half* UH    = hs + HO_UH;
    __half* UL    = hs + HO_UL;
    __half* GHp   = hs + HO_GH;
    __half* GLp   = hs + HO_GL;
    __half* HHp   = hs + HO_HH;
    __half* HLp   = hs + HO_HL;

    cudaFuncSetAttribute(hgemm_kernel,
                         cudaFuncAttributeMaxDynamicSharedMemorySize, HG_SMEM);

    embed_kernel<<<2048, 256>>>(tok, emb, gh);
    split_kernel<<<2048, 256>>>(W_in, WinH, WinL, WIN_SZ);
    split_kernel<<<2048, 256>>>(W_out, WoutH, WoutL, WOUT_SZ);
    split_kernel<<<64, 256>>>(head_w, HeadH, HeadL, HEAD_SZ);

    for (int L = 0; L < NL; L++) {
        rmsnorm_kernel<<<TT, 256>>>(gh, norm_w + L * DM, UH, UL);
        hgemm_kernel<<<dim3((DPROJ + HBN_ - 1) / HBN_, TT / HBM_), 256, HG_SMEM>>>(
            UH, UL, WinH + (size_t)L * DM * DPROJ, WinL + (size_t)L * DM * DPROJ,
            b_in + L * DPROJ, nullptr, gzx, TT, DPROJ, DM);
        conv_kernel<<<dim3((CONV + 127) / 128, SS / CTS, BB), 128>>>(
            gzx, conv_w + L * CONV * KC, conv_b + L * CONV, gxc, gB, gC);
        dt_kernel<<<(TT * NH + 255) / 256, 256>>>(
            gzx, dt_bias + L * NH, A_log + L * NH, gdt, gdA);
        scan_kernel<<<BB * NH * 4, 128>>>(gxc, gB, gC, gdt, gdA,
                                          D_param + L * NH, gy);
        gate_norm_kernel<<<TT, 256>>>(gy, gzx, gnorm_w + L * DIN, GHp, GLp);
        hgemm_kernel<<<dim3(DM / HBN_, TT / HBM_), 256, HG_SMEM>>>(
            GHp, GLp, WoutH + (size_t)L * DIN * DM, WoutL + (size_t)L * DIN * DM,
            b_out + L * DM, gh, gh, TT, DM, DIN);
    }

    split_kernel<<<2048, 256>>>(gh, HHp, HLp, U_SZ);
    hgemm_kernel<<<dim3(1, TT / HBM_), 256, HG_SMEM>>>(
        HHp, HLp, HeadH, HeadL, head_b, nullptr, (float*)d_out, TT, VOCAB, DM);
}

// round 7
// speedup vs baseline: 1.1071x; 1.1071x over previous
#include <cuda_runtime.h>
#include <cuda_fp16.h>
#include <cuda_pipeline.h>
#include <mma.h>
#include <math.h>

using namespace nvcuda;

// ---------------- model constants ----------------
#define VOCAB   64
#define DM      512
#define NS      32
#define NH      16
#define NL      4
#define DIN     1024
#define PH      64
#define CONV    1088
#define KC      4
#define DPROJ   2128
#define BB      4
#define SS      1024
#define TT      (BB*SS)
#define EPSV    1e-5f

// ---------------- fp32 scratch ----------------
#define OFF_H    0u
#define OFF_ZX   (OFF_H  + TT*DM)
#define OFF_XC   (OFF_ZX + TT*DPROJ)
#define OFF_B    (OFF_XC + TT*DIN)
#define OFF_C    (OFF_B  + TT*NS)
#define OFF_DT   (OFF_C  + TT*NS)
#define OFF_DA   (OFF_DT + TT*NH)
#define OFF_Y    (OFF_DA + TT*NH)
#define SCRATCH_TOTAL (OFF_Y + TT*DIN)
__device__ float g_scratch[SCRATCH_TOTAL];

// ---------------- fp16 hi/lo scratch ----------------
#define WIN_SZ  (NL*DM*DPROJ)
#define WOUT_SZ (NL*DIN*DM)
#define HEAD_SZ (DM*VOCAB)
#define U_SZ    (TT*DM)
#define G_SZ    (TT*DIN)

#define HO_WINH  0u
#define HO_WINL  (HO_WINH + WIN_SZ)
#define HO_WOUTH (HO_WINL + WIN_SZ)
#define HO_WOUTL (HO_WOUTH + WOUT_SZ)
#define HO_HEADH (HO_WOUTL + WOUT_SZ)
#define HO_HEADL (HO_HEADH + HEAD_SZ)
#define HO_UH    (HO_HEADL + HEAD_SZ)
#define HO_UL    (HO_UH + U_SZ)
#define HO_GH    (HO_UL + U_SZ)
#define HO_GL    (HO_GH + G_SZ)
#define HO_HH    (HO_GL + G_SZ)
#define HO_HL    (HO_HH + U_SZ)
#define HALF_TOTAL (HO_HL + U_SZ)
__device__ __half g_half[HALF_TOTAL];

// ---------------- embedding gather ----------------
__global__ void embed_kernel(const int* __restrict__ tok,
                             const float* __restrict__ emb,
                             float* __restrict__ h) {
    for (int i = blockIdx.x * blockDim.x + threadIdx.x; i < TT * DM;
         i += gridDim.x * blockDim.x) {
        int row = i >> 9;
        int d   = i & (DM - 1);
        h[i] = emb[tok[row] * DM + d];
    }
}

// ---------------- fp32 -> fp16 hi/lo split ----------------
__global__ void split_kernel(const float* __restrict__ x,
                             __half* __restrict__ hi,
                             __half* __restrict__ lo, int n) {
    for (int i = blockIdx.x * blockDim.x + threadIdx.x; i < n;
         i += gridDim.x * blockDim.x) {
        float v = x[i];
        __half p = __float2half_rn(v);
        hi[i] = p;
        lo[i] = __float2half_rn(v - __half2float(p));
    }
}

// ---------------- rmsnorm over D_MODEL=512 -> hi/lo fp16 --------------
__global__ void rmsnorm_kernel(const float* __restrict__ x,
                               const float* __restrict__ w,
                               __half* __restrict__ uhi,
                               __half* __restrict__ ulo) {
    int row = blockIdx.x;
    const float* xr = x + (size_t)row * DM;
    int t = threadIdx.x;
    float v0 = xr[t];
    float v1 = xr[t + 256];
    float ss = v0 * v0 + v1 * v1;
    #pragma unroll
    for (int o = 16; o; o >>= 1) ss += __shfl_down_sync(0xffffffffu, ss, o);
    __shared__ float red[8];
    if ((t & 31) == 0) red[t >> 5] = ss;
    __syncthreads();
    if (t < 8) {
        float r = red[t];
        #pragma unroll
        for (int o = 4; o; o >>= 1) r += __shfl_down_sync(0xffu, r, o);
        if (t == 0) red[0] = r;
    }
    __syncthreads();
    float scale = rsqrtf(red[0] * (1.0f / DM) + EPSV);
    float o0 = v0 * scale * w[t];
    float o1 = v1 * scale * w[t + 256];
    __half p0 = __float2half_rn(o0);
    __half p1 = __float2half_rn(o1);
    uhi[(size_t)row * DM + t]       = p0;
    ulo[(size_t)row * DM + t]       = __float2half_rn(o0 - __half2float(p0));
    uhi[(size_t)row * DM + t + 256] = p1;
    ulo[(size_t)row * DM + t + 256] = __float2half_rn(o1 - __half2float(p1));
}

// ---------------- fp16-split WMMA GEMM v2 ----------------
// C[M,N] = (Ah+Al)[M,K] @ (Bh+Bl)[K,N] + bias[N] (+res)
// Block tile 128x64, k-tile 32. 128 threads = 4 warps, each warp tile 32x64.
// 2-stage cp.async double buffer, dynamic smem.
#define HBM_ 128
#define HBN_ 64
#define HBK_ 32
#define ASTR 40
#define BSTR 72
#define A_STG (HBM_*ASTR)          // 5120 halves per stage
#define B_STG (HBK_*BSTR)          // 2304 halves per stage
#define HG_SMEM ((4*A_STG + 4*B_STG) * 2)   // 59392 bytes

extern __shared__ __align__(16) unsigned char hg_smem[];

__global__ void __launch_bounds__(128, 3)
hgemm_kernel(const __half* __restrict__ Ah, const __half* __restrict__ Al,
             const __half* __restrict__ Bh, const __half* __restrict__ Bl,
             const float* __restrict__ bias, const float* __restrict__ res,
             float* __restrict__ C, int M, int N, int K)
{
    __half* sAh = (__half*)hg_smem;          // [2][A_STG]
    __half* sAl = sAh + 2 * A_STG;
    __half* sBh = sAl + 2 * A_STG;           // [2][B_STG]
    __half* sBl = sBh + 2 * B_STG;
    float*  sOut = (float*)hg_smem;

    int tid = threadIdx.x;
    int bm = blockIdx.y * HBM_;
    int bn = blockIdx.x * HBN_;

    int lane = tid & 31;
    int warp = tid >> 5;
    int wm = warp * 32;                      // warp covers rows wm..wm+31, all 64 cols

    // A tile: 128x32 halves -> 512 16B chunks per array; 128 threads -> 4 each
    int a_row = tid >> 2;                    // 0..31 (+32/64/96)
    int a_col = (tid & 3) * 8;
    // B tile: 32x64 halves -> 256 chunks; 2 each
    int b_row = tid >> 3;                    // 0..15 (+16)
    int b_col = (tid & 7) * 8;
    bool bvalid = (bn + b_col + 8 <= N);

    wmma::fragment<wmma::accumulator, 16, 16, 16, float> acc[2][4];
    #pragma unroll
    for (int mi = 0; mi < 2; mi++) {
        #pragma unroll
        for (int ni = 0; ni < 4; ni++) {
            wmma::fill_fragment(acc[mi][ni], 0.0f);
        }
    }

    int KT = K / HBK_;

    // zero-fill invalid B region once for both stages (stays zero; loads skip it)
    if (!bvalid) {
        uint4 z;
        z.x = 0u; z.y = 0u; z.z = 0u; z.w = 0u;
        *(uint4*)(sBh + (b_row +  0) * BSTR + b_col) = z;
        *(uint4*)(sBh + (b_row + 16) * BSTR + b_col) = z;
        *(uint4*)(sBh + B_STG + (b_row +  0) * BSTR + b_col) = z;
        *(uint4*)(sBh + B_STG + (b_row + 16) * BSTR + b_col) = z;
        *(uint4*)(sBl + (b_row +  0) * BSTR + b_col) = z;
        *(uint4*)(sBl + (b_row + 16) * BSTR + b_col) = z;
        *(uint4*)(sBl + B_STG + (b_row +  0) * BSTR + b_col) = z;
        *(uint4*)(sBl + B_STG + (b_row + 16) * BSTR + b_col) = z;
    }
    __syncthreads();

    // ---- prologue: async-load stage 0 ----
    {
        int k0 = 0;
        #pragma unroll
        for (int rr = 0; rr < 4; rr++) {
            int r = a_row + rr * 32;
            __pipeline_memcpy_async(sAh + r * ASTR + a_col,
                                    Ah + (size_t)(bm + r) * K + k0 + a_col, 16);
            __pipeline_memcpy_async(sAl + r * ASTR + a_col,
                                    Al + (size_t)(bm + r) * K + k0 + a_col, 16);
        }
        if (bvalid) {
            #pragma unroll
            for (int rr = 0; rr < 2; rr++) {
                int r = b_row + rr * 16;
                __pipeline_memcpy_async(sBh + r * BSTR + b_col,
                                        Bh + (size_t)(k0 + r) * N + bn + b_col, 16);
                __pipeline_memcpy_async(sBl + r * BSTR + b_col,
                                        Bl + (size_t)(k0 + r) * N + bn + b_col, 16);
            }
        }
        __pipeline_commit();
    }

    for (int kt = 0; kt < KT; kt++) {
        if (kt + 1 < KT) {
            int st = (kt + 1) & 1;
            int k0 = (kt + 1) * HBK_;
            __half* dAh = sAh + st * A_STG;
            __half* dAl = sAl + st * A_STG;
            __half* dBh = sBh + st * B_STG;
            __half* dBl = sBl + st * B_STG;
            #pragma unroll
            for (int rr = 0; rr < 4; rr++) {
                int r = a_row + rr * 32;
                __pipeline_memcpy_async(dAh + r * ASTR + a_col,
                                        Ah + (size_t)(bm + r) * K + k0 + a_col, 16);
                __pipeline_memcpy_async(dAl + r * ASTR + a_col,
                                        Al + (size_t)(bm + r) * K + k0 + a_col, 16);
            }
            if (bvalid) {
                #pragma unroll
                for (int rr = 0; rr < 2; rr++) {
                    int r = b_row + rr * 16;
                    __pipeline_memcpy_async(dBh + r * BSTR + b_col,
                                            Bh + (size_t)(k0 + r) * N + bn + b_col, 16);
                    __pipeline_memcpy_async(dBl + r * BSTR + b_col,
                                            Bl + (size_t)(k0 + r) * N + bn + b_col, 16);
                }
            }
            __pipeline_commit();
            __pipeline_wait_prior(1);
        } else {
            __pipeline_wait_prior(0);
        }
        __syncthreads();

        // ---- compute stage kt&1 ----
        {
            int st = kt & 1;
            __half* pAh = sAh + st * A_STG;
            __half* pAl = sAl + st * A_STG;
            __half* pBh = sBh + st * B_STG;
            __half* pBl = sBl + st * B_STG;
            #pragma unroll
            for (int kc = 0; kc < 2; kc++) {
                wmma::fragment<wmma::matrix_a, 16, 16, 16, half, wmma::row_major> fah[2];
                wmma::fragment<wmma::matrix_a, 16, 16, 16, half, wmma::row_major> fal[2];
                #pragma unroll
                for (int mi = 0; mi < 2; mi++) {
                    wmma::load_matrix_sync(fah[mi], pAh + (wm + mi * 16) * ASTR + kc * 16, ASTR);
                    wmma::load_matrix_sync(fal[mi], pAl + (wm + mi * 16) * ASTR + kc * 16, ASTR);
                }
                #pragma unroll
                for (int ni = 0; ni < 4; ni++) {
                    wmma::fragment<wmma::matrix_b, 16, 16, 16, half, wmma::row_major> fbh;
                    wmma::fragment<wmma::matrix_b, 16, 16, 16, half, wmma::row_major> fbl;
                    wmma::load_matrix_sync(fbh, pBh + (kc * 16) * BSTR + ni * 16, BSTR);
                    wmma::load_matrix_sync(fbl, pBl + (kc * 16) * BSTR + ni * 16, BSTR);
                    #pragma unroll
                    for (int mi = 0; mi < 2; mi++) {
                        wmma::mma_sync(acc[mi][ni], fah[mi], fbh, acc[mi][ni]);
                        wmma::mma_sync(acc[mi][ni], fah[mi], fbl, acc[mi][ni]);
                        wmma::mma_sync(acc[mi][ni], fal[mi], fbh, acc[mi][ni]);
                    }
                }
            }
        }
        __syncthreads();
    }

    // ---- epilogue: park accumulators in smem, then guarded global stores ----
    float* myOut = sOut + warp * (32 * 64);
    #pragma unroll
    for (int mi = 0; mi < 2; mi++) {
        #pragma unroll
        for (int ni = 0; ni < 4; ni++) {
            wmma::store_matrix_sync(myOut + mi * 16 * 64 + ni * 16,
                                    acc[mi][ni], 64, wmma::mem_row_major);
        }
    }
    __syncwarp();
    #pragma unroll
    for (int half_ = 0; half_ < 2; half_++) {
        int colg = bn + half_ * 32 + lane;
        if (colg < N) {
            float bc = bias[colg];
            #pragma unroll 4
            for (int r = 0; r < 32; r++) {
                int rowg = bm + wm + r;
                float v = myOut[r * 64 + half_ * 32 + lane] + bc;
                size_t off = (size_t)rowg * N + colg;
                if (res) v += res[off];
                C[off] = v;
            }
        }
    }
}

// ---------------- causal depthwise conv + silu (sliding window) -------------
#define CTS 128
__global__ void __launch_bounds__(128)
conv_kernel(const float* __restrict__ zx,
            const float* __restrict__ cw,
            const float* __restrict__ cb,
            float* __restrict__ xc,
            float* __restrict__ Bm,
            float* __restrict__ Cm) {
    int c = blockIdx.x * 128 + threadIdx.x;
    if (c >= CONV) return;
    int b = blockIdx.z;
    int t0 = blockIdx.y * CTS;

    float w0 = cw[c * KC + 0];
    float w1 = cw[c * KC + 1];
    float w2 = cw[c * KC + 2];
    float w3 = cw[c * KC + 3];
    float bias = cb[c];

    const float* base = zx + (size_t)(b * SS) * DPROJ + DIN + c;

    float x0 = (t0 - 3 >= 0) ? base[(size_t)(t0 - 3) * DPROJ] : 0.0f;
    float x1 = (t0 - 2 >= 0) ? base[(size_t)(t0 - 2) * DPROJ] : 0.0f;
    float x2 = (t0 - 1 >= 0) ? base[(size_t)(t0 - 1) * DPROJ] : 0.0f;

    for (int t = t0; t < t0 + CTS; t++) {
        float x3 = base[(size_t)t * DPROJ];
        float acc = bias + w0 * x0 + w1 * x1 + w2 * x2 + w3 * x3;
        float s = acc / (1.0f + expf(-acc));
        int row = b * SS + t;
        if (c < DIN)            xc[(size_t)row * DIN + c] = s;
        else if (c < DIN + NS)  Bm[(size_t)row * NS + (c - DIN)] = s;
        else                    Cm[(size_t)row * NS + (c - DIN - NS)] = s;
        x0 = x1;
        x1 = x2;
        x2 = x3;
    }
}

// ---------------- dt softplus + dA ----------------
__global__ void dt_kernel(const float* __restrict__ zx,
                          const float* __restrict__ dtb,
                          const float* __restrict__ Alog,
                          float* __restrict__ dtO,
                          float* __restrict__ dAO) {
    int i = blockIdx.x * blockDim.x + threadIdx.x;
    if (i >= TT * NH) return;
    int row = i >> 4;
    int hh = i & 15;
    float v = zx[(size_t)row * DPROJ + DIN + CONV + hh] + dtb[hh];
    float sp = (v > 20.0f) ? v : log1pf(expf(v));
    dtO[i] = sp;
    dAO[i] = expf(sp * (-expf(Alog[hh])));
}

// ---------------- SSD sequential scan -----------------------------------
#define SCAN_TS 16
__global__ void __launch_bounds__(128)
scan_kernel(const float* __restrict__ xc, const float* __restrict__ Bm,
            const float* __restrict__ Cm, const float* __restrict__ dt,
            const float* __restrict__ dA, const float* __restrict__ Dp,
            float* __restrict__ y) {
    int blk = blockIdx.x;
    int pch = blk & 3;
    int bh  = blk >> 2;
    int b   = bh >> 4;
    int hh  = bh & 15;
    int tid = threadIdx.x;
    int pl  = tid >> 3;
    int ns  = tid & 7;
    int p   = pch * 16 + pl;

    __shared__ float4 sB[SCAN_TS][8];
    __shared__ float4 sC[SCAN_TS][8];
    __shared__ float  sx[SCAN_TS][16];
    __shared__ float  sdA[SCAN_TS];
    __shared__ float  sdt[SCAN_TS];

    float h0 = 0.f, h1 = 0.f, h2 = 0.f, h3 = 0.f;
    float dparam = Dp[hh];
    int rowbase = b * SS;

    for (int t0 = 0; t0 < SS; t0 += SCAN_TS) {
        {
            int ts = tid >> 3;
            int nf = tid & 7;
            int row = rowbase + t0 + ts;
            sB[ts][nf] = ((const float4*)(Bm + (size_t)row * NS))[nf];
            sC[ts][nf] = ((const float4*)(Cm + (size_t)row * NS))[nf];
        }
        for (int i = tid; i < SCAN_TS * 16; i += 128) {
            int ts = i >> 4;
            int ppl = i & 15;
            int row = rowbase + t0 + ts;
            sx[ts][ppl] = xc[(size_t)row * DIN + hh * PH + pch * 16 + ppl];
        }
        if (tid < SCAN_TS) {
            int row = rowbase + t0 + tid;
            sdA[tid] = dA[row * NH + hh];
            sdt[tid] = dt[row * NH + hh];
        }
        __syncthreads();

        #pragma unroll 4
        for (int ts = 0; ts < SCAN_TS; ts++) {
            float a    = sdA[ts];
            float xval = sx[ts][pl];
            float dtx  = sdt[ts] * xval;
            float4 Bv = sB[ts][ns];
            float4 Cv = sC[ts][ns];
            h0 = fmaf(a, h0, dtx * Bv.x);
            h1 = fmaf(a, h1, dtx * Bv.y);
            h2 = fmaf(a, h2, dtx * Bv.z);
            h3 = fmaf(a, h3, dtx * Bv.w);
            float acc = h0 * Cv.x;
            acc = fmaf(h1, Cv.y, acc);
            acc = fmaf(h2, Cv.z, acc);
            acc = fmaf(h3, Cv.w, acc);
            acc += __shfl_down_sync(0xffffffffu, acc, 4, 8);
            acc += __shfl_down_sync(0xffffffffu, acc, 2, 8);
            acc += __shfl_down_sync(0xffffffffu, acc, 1, 8);
            if (ns == 0) {
                int row = rowbase + t0 + ts;
                y[(size_t)row * DIN + hh * PH + p] = fmaf(xval, dparam, acc);
            }
        }
        __syncthreads();
    }
}

// ---------------- gate (y * silu(z)) + rmsnorm over D_INNER -> hi/lo --------
__global__ void gate_norm_kernel(const float* __restrict__ y,
                                 const float* __restrict__ zx,
                                 const float* __restrict__ gw,
                                 __half* __restrict__ ghi,
                                 __half* __restrict__ glo) {
    int row = blockIdx.x;
    __shared__ float sv[DIN];
    __shared__ float red[8];
    float ss = 0.0f;
    for (int c = threadIdx.x; c < DIN; c += blockDim.x) {
        float z = zx[(size_t)row * DPROJ + c];
        float v = y[(size_t)row * DIN + c] * (z / (1.0f + expf(-z)));
        sv[c] = v;
        ss += v * v;
    }
    #pragma unroll
    for (int o = 16; o; o >>= 1) ss += __shfl_down_sync(0xffffffffu, ss, o);
    if ((threadIdx.x & 31) == 0) red[threadIdx.x >> 5] = ss;
    __syncthreads();
    if (threadIdx.x < 8) {
        float r = red[threadIdx.x];
        #pragma unroll
        for (int o = 4; o; o >>= 1) r += __shfl_down_sync(0xffu, r, o);
        if (threadIdx.x == 0) red[0] = r;
    }
    __syncthreads();
    float scale = rsqrtf(red[0] * (1.0f / DIN) + EPSV);
    for (int c = threadIdx.x; c < DIN; c += blockDim.x) {
        float v = sv[c] * scale * gw[c];
        __half p = __float2half_rn(v);
        ghi[(size_t)row * DIN + c] = p;
        glo[(size_t)row * DIN + c] = __float2half_rn(v - __half2float(p));
    }
}

// ---------------- launch ----------------
extern "C" void kernel_launch(void* const* d_in, const int* in_sizes, int n_in,
                              void* d_out, int out_size) {
    const int*   tok     = (const int*)  d_in[0];
    const float* emb     = (const float*)d_in[1];
    const float* norm_w  = (const float*)d_in[2];
    const float* W_in    = (const float*)d_in[3];
    const float* b_in    = (const float*)d_in[4];
    const float* conv_w  = (const float*)d_in[5];
    const float* conv_b  = (const float*)d_in[6];
    const float* dt_bias = (const float*)d_in[7];
    const float* A_log   = (const float*)d_in[8];
    const float* D_param = (const float*)d_in[9];
    const float* gnorm_w = (const float*)d_in[10];
    const float* W_out   = (const float*)d_in[11];
    const float* b_out   = (const float*)d_in[12];
    const float* head_w  = (const float*)d_in[13];
    const float* head_b  = (const float*)d_in[14];

    float* scratch = nullptr;
    cudaGetSymbolAddress((void**)&scratch, g_scratch);
    __half* hs = nullptr;
    cudaGetSymbolAddress((void**)&hs, g_half);

    float* gh  = scratch + OFF_H;
    float* gzx = scratch + OFF_ZX;
    float* gxc = scratch + OFF_XC;
    float* gB  = scratch + OFF_B;
    float* gC  = scratch + OFF_C;
    float* gdt = scratch + OFF_DT;
    float* gdA = scratch + OFF_DA;
    float* gy  = scratch + OFF_Y;

    __half* WinH  = hs + HO_WINH;
    __half* WinL  = hs + HO_WINL;
    __half* WoutH = hs + HO_WOUTH;
    __half* WoutL = hs + HO_WOUTL;
    __half* HeadH = hs + HO_HEADH;
    __half* HeadL = hs + HO_HEADL;
    __half* UH    = hs + HO_UH;
    __half* UL    = hs + HO_UL;
    __half* GHp   = hs + HO_GH;
    __half* GLp   = hs + HO_GL;
    __half* HHp   = hs + HO_HH;
    __half* HLp   = hs + HO_HL;

    cudaFuncSetAttribute(hgemm_kernel,
                         cudaFuncAttributeMaxDynamicSharedMemorySize, HG_SMEM);

    // Launch order puts the first hgemm at launch index 3 so ncu profiles it.
    split_kernel<<<2048, 256>>>(W_in, WinH, WinL, WIN_SZ);       // 0
    embed_kernel<<<2048, 256>>>(tok, emb, gh);                   // 1

    for (int L = 0; L < NL; L++) {
        rmsnorm_kernel<<<TT, 256>>>(gh, norm_w + L * DM, UH, UL);        // 2 (L=0)
        hgemm_kernel<<<dim3((DPROJ + HBN_ - 1) / HBN_, TT / HBM_), 128, HG_SMEM>>>(
            UH, UL, WinH + (size_t)L * DM * DPROJ, WinL + (size_t)L * DM * DPROJ,
            b_in + L * DPROJ, nullptr, gzx, TT, DPROJ, DM);              // 3 (L=0)
        if (L == 0) {
            split_kernel<<<2048, 256>>>(W_out, WoutH, WoutL, WOUT_SZ);
            split_kernel<<<64, 256>>>(head_w, HeadH, HeadL, HEAD_SZ);
        }
        conv_kernel<<<dim3((CONV + 127) / 128, SS / CTS, BB), 128>>>(
            gzx, conv_w + L * CONV * KC, conv_b + L * CONV, gxc, gB, gC);
        dt_kernel<<<(TT * NH + 255) / 256, 256>>>(
            gzx, dt_bias + L * NH, A_log + L * NH, gdt, gdA);
        scan_kernel<<<BB * NH * 4, 128>>>(gxc, gB, gC, gdt, gdA,
                                          D_param + L * NH, gy);
        gate_norm_kernel<<<TT, 256>>>(gy, gzx, gnorm_w + L * DIN, GHp, GLp);
        hgemm_kernel<<<dim3(DM / HBN_, TT / HBM_), 128, HG_SMEM>>>(
            GHp, GLp, WoutH + (size_t)L * DIN * DM, WoutL + (size_t)L * DIN * DM,
            b_out + L * DM, gh, gh, TT, DM, DIN);
    }

    split_kernel<<<2048, 256>>>(gh, HHp, HLp, U_SZ);
    hgemm_kernel<<<dim3(1, TT / HBM_), 128, HG_SMEM>>>(
        HHp, HLp, HeadH, HeadL, head_b, nullptr, (float*)d_out, TT, VOCAB, DM);
}